// round 2
// baseline (speedup 1.0000x reference)
#include <cuda_runtime.h>
#include <cstdint>
#include <cstddef>

#define TSTEPS 32
#define INF    27
#define HID    10

// ---------- packed f32x2 helpers (Blackwell) ----------
__device__ __forceinline__ unsigned long long pk2(float a, float b){
  unsigned long long r;
  asm("mov.b64 %0, {%1, %2};" : "=l"(r) : "f"(a), "f"(b));
  return r;
}
__device__ __forceinline__ float2 unpk2(unsigned long long v){
  float2 r;
  asm("mov.b64 {%0, %1}, %2;" : "=f"(r.x), "=f"(r.y) : "l"(v));
  return r;
}
__device__ __forceinline__ unsigned long long ffma2(unsigned long long a, unsigned long long b, unsigned long long c){
  unsigned long long d;
  asm("fma.rn.f32x2 %0, %1, %2, %3;" : "=l"(d) : "l"(a), "l"(b), "l"(c));
  return d;
}
__device__ __forceinline__ void cp8(uint32_t saddr, const void* gptr){
  asm volatile("cp.async.ca.shared.global [%0], [%1], 8;" :: "r"(saddr), "l"(gptr));
}
__device__ __forceinline__ unsigned long long shflx1_u64(unsigned long long v){
  uint32_t lo = (uint32_t)v, hi = (uint32_t)(v >> 32);
  lo = __shfl_xor_sync(0xFFFFFFFFu, lo, 1);
  hi = __shfl_xor_sync(0xFFFFFFFFu, hi, 1);
  return ((unsigned long long)hi << 32) | lo;
}
// sigmoid / tanh via MUFU.EX2 + MUFU.RCP (near-full precision)
__device__ __forceinline__ float sigf(float v){
  return __fdividef(1.f, 1.f + __expf(-v));
}
__device__ __forceinline__ float tanhfast(float v){
  return __fdividef(2.f, 1.f + __expf(-2.f*v)) - 1.f;
}

// Block: 128 threads. Lanes pair up: lanes (2t, 2t+1) share batch elements
// (2p, 2p+1) where p = tid>>1; lane parity selects which 5 hidden units (k)
// it computes. 64 pairs -> 128 batch elements per block.
__global__ void __launch_bounds__(128) lstm_fused_kernel(
    const float* __restrict__ word,
    const float* __restrict__ W_ih, const float* __restrict__ W_hh,
    const float* __restrict__ b_ih, const float* __restrict__ b_hh,
    const float* __restrict__ W_fc, const float* __restrict__ b_fc,
    const float* __restrict__ W_out, const float* __restrict__ b_out,
    float* __restrict__ out, int Bn)
{
  // weights pre-duplicated (w,w) as u64 so LDS.128 yields 2 FFMA2 operands
  __shared__ __align__(16) unsigned long long s_wih[40*28]; // rows padded 27->28, pad=0
  __shared__ __align__(16) unsigned long long s_whh[40*12]; // rows padded 10->12, pad=0
  __shared__ __align__(16) unsigned long long s_b[40];      // b_ih+b_hh, duplicated
  __shared__ float s_wfc[50], s_bfc[5], s_wout[5], s_bout[1];
  __shared__ __align__(16) float s_x[2][128*INF];           // double-buffered x staging

  const int tid  = threadIdx.x;
  const int half = tid & 1;          // which 5 k's this lane owns
  const int pr   = tid >> 1;         // pair index (0..63)
  const int kbase = half * 5;

  for (int idx = tid; idx < 40*28; idx += 128){
    int r = idx / 28, j = idx - r*28;
    float w = (j < 27) ? W_ih[r*27 + j] : 0.f;
    s_wih[idx] = pk2(w, w);
  }
  for (int idx = tid; idx < 40*12; idx += 128){
    int r = idx / 12, j = idx - r*12;
    float w = (j < 10) ? W_hh[r*10 + j] : 0.f;
    s_whh[idx] = pk2(w, w);
  }
  if (tid < 40){ float b = b_ih[tid] + b_hh[tid]; s_b[tid] = pk2(b, b); }
  if (tid < 50) s_wfc[tid] = W_fc[tid];
  if (tid < 5) { s_bfc[tid] = b_fc[tid]; s_wout[tid] = W_out[tid]; }
  if (tid == 0) s_bout[0] = b_out[0];

  const int blockElem = blockIdx.x * 128;
  const uint32_t sx0 = (uint32_t)__cvta_generic_to_shared(&s_x[0][0]);

  // stage t=0 into buffer 0 (1728 float2 per block-step)
  {
    const float2* src = (const float2*)(word + ((size_t)blockElem) * INF);
    #pragma unroll
    for (int m = 0; m < 14; m++){
      int i2 = m*128 + tid;
      if (i2 < 1728) cp8(sx0 + (uint32_t)(i2*8), src + i2);
    }
    asm volatile("cp.async.commit_group;");
  }

  // packed recurrent state: full h (both halves, exchanged via shfl), own-c only
  unsigned long long hp[12], hn[5];        // h padded to 12 (pads = 0)
  float c0a[5], c1a[5];                    // cell state for my 5 k, 2 elems
  #pragma unroll
  for (int k = 0; k < 12; k++) hp[k] = 0ull;
  #pragma unroll
  for (int k = 0; k < 5; k++){ c0a[k] = 0.f; c1a[k] = 0.f; }

  const int e0 = 2*pr;

  #pragma unroll 1
  for (int t = 0; t < TSTEPS; t++){
    if (t + 1 < TSTEPS){
      const float2* src = (const float2*)(word + ((size_t)(t+1)*Bn + blockElem) * INF);
      uint32_t dst = sx0 + (uint32_t)(((t+1)&1) * (128*INF*4));
      #pragma unroll
      for (int m = 0; m < 14; m++){
        int i2 = m*128 + tid;
        if (i2 < 1728) cp8(dst + (uint32_t)(i2*8), src + i2);
      }
      asm volatile("cp.async.commit_group;");
      asm volatile("cp.async.wait_group 1;");  // buffer for step t is done
    } else {
      asm volatile("cp.async.wait_group 0;");
    }
    __syncthreads();

    // pack this pair's x into registers (both lanes of a pair load the same
    // addresses -> 2-way broadcast, conflict-free across pairs)
    const float* xb = &s_x[t & 1][0];
    unsigned long long xj[28];
    #pragma unroll
    for (int j = 0; j < 27; j++)
      xj[j] = pk2(xb[e0*INF + j], xb[e0*INF + INF + j]);
    xj[27] = 0ull;

    #pragma unroll
    for (int kk = 0; kk < 5; kk++){
      const int k = kbase + kk;
      unsigned long long ai = s_b[k], af = s_b[k+10], ag = s_b[k+20], ao = s_b[k+30];
      const ulonglong2* wi = (const ulonglong2*)(s_wih + (k     )*28);
      const ulonglong2* wf = (const ulonglong2*)(s_wih + (k + 10)*28);
      const ulonglong2* wg = (const ulonglong2*)(s_wih + (k + 20)*28);
      const ulonglong2* wo = (const ulonglong2*)(s_wih + (k + 30)*28);
      #pragma unroll
      for (int m = 0; m < 14; m++){
        ulonglong2 vi = wi[m], vf = wf[m], vg = wg[m], vo = wo[m];
        ai = ffma2(vi.x, xj[2*m], ai); ai = ffma2(vi.y, xj[2*m+1], ai);
        af = ffma2(vf.x, xj[2*m], af); af = ffma2(vf.y, xj[2*m+1], af);
        ag = ffma2(vg.x, xj[2*m], ag); ag = ffma2(vg.y, xj[2*m+1], ag);
        ao = ffma2(vo.x, xj[2*m], ao); ao = ffma2(vo.y, xj[2*m+1], ao);
      }
      const ulonglong2* ui = (const ulonglong2*)(s_whh + (k     )*12);
      const ulonglong2* uf = (const ulonglong2*)(s_whh + (k + 10)*12);
      const ulonglong2* ug = (const ulonglong2*)(s_whh + (k + 20)*12);
      const ulonglong2* uo = (const ulonglong2*)(s_whh + (k + 30)*12);
      #pragma unroll
      for (int m = 0; m < 6; m++){
        ulonglong2 vi = ui[m], vf = uf[m], vg = ug[m], vo = uo[m];
        ai = ffma2(vi.x, hp[2*m], ai); ai = ffma2(vi.y, hp[2*m+1], ai);
        af = ffma2(vf.x, hp[2*m], af); af = ffma2(vf.y, hp[2*m+1], af);
        ag = ffma2(vg.x, hp[2*m], ag); ag = ffma2(vg.y, hp[2*m+1], ag);
        ao = ffma2(vo.x, hp[2*m], ao); ao = ffma2(vo.y, hp[2*m+1], ao);
      }
      float2 gi = unpk2(ai), gf = unpk2(af), gg = unpk2(ag), go = unpk2(ao);
      float i0 = sigf(gi.x), i1 = sigf(gi.y);
      float f0 = sigf(gf.x), f1 = sigf(gf.y);
      float g0 = tanhfast(gg.x), g1 = tanhfast(gg.y);
      float o0 = sigf(go.x), o1 = sigf(go.y);
      float cn0 = fmaf(f0, c0a[kk], i0*g0);
      float cn1 = fmaf(f1, c1a[kk], i1*g1);
      float h0  = o0 * tanhfast(cn0);
      float h1  = o1 * tanhfast(cn1);
      c0a[kk] = fmaxf(cn0, 0.f);             // ReLU on carried cell state
      c1a[kk] = fmaxf(cn1, 0.f);
      hn[kk]  = pk2(fmaxf(h0, 0.f), fmaxf(h1, 0.f)); // ReLU on carried hidden
    }
    // exchange halves: each lane gets partner's 5 h-pairs -> full hp[0..9]
    const int ob = 5 - kbase;   // partner's base (0<->5)
    #pragma unroll
    for (int kk = 0; kk < 5; kk++){
      unsigned long long other = shflx1_u64(hn[kk]);
      hp[kbase + kk] = hn[kk];
      hp[ob + kk]    = other;
    }
    __syncthreads();   // all reads of this x buffer done before it is re-staged
  }

  // ---- head: FC(10->5) -> ReLU -> Linear(5->1) -> sigmoid ----
  if (half == 0){
    float h0s[10], h1s[10];
    #pragma unroll
    for (int k = 0; k < 10; k++){ float2 v = unpk2(hp[k]); h0s[k] = v.x; h1s[k] = v.y; }
    float z0 = s_bout[0], z1 = s_bout[0];
    #pragma unroll
    for (int u = 0; u < 5; u++){
      float y0 = s_bfc[u], y1 = s_bfc[u];
      #pragma unroll
      for (int k = 0; k < 10; k++){
        y0 = fmaf(s_wfc[u*10 + k], h0s[k], y0);
        y1 = fmaf(s_wfc[u*10 + k], h1s[k], y1);
      }
      y0 = fmaxf(y0, 0.f); y1 = fmaxf(y1, 0.f);
      z0 = fmaf(s_wout[u], y0, z0);
      z1 = fmaf(s_wout[u], y1, z1);
    }
    const int b0 = blockElem + e0;
    if (b0     < Bn) out[b0]     = sigf(z0);
    if (b0 + 1 < Bn) out[b0 + 1] = sigf(z1);
  }
}

extern "C" void kernel_launch(void* const* d_in, const int* in_sizes, int n_in,
                              void* d_out, int out_size) {
  const float* word  = (const float*)d_in[0];
  const float* W_ih  = (const float*)d_in[1];
  const float* W_hh  = (const float*)d_in[2];
  const float* b_ih  = (const float*)d_in[3];
  const float* b_hh  = (const float*)d_in[4];
  const float* W_fc  = (const float*)d_in[5];
  const float* b_fc  = (const float*)d_in[6];
  const float* W_out = (const float*)d_in[7];
  const float* b_out = (const float*)d_in[8];
  float* out = (float*)d_out;

  const int Bn = in_sizes[0] / (TSTEPS * INF);   // 65536
  const int blocks = (Bn + 127) / 128;           // 512 blocks of 128 threads

  lstm_fused_kernel<<<blocks, 128>>>(word, W_ih, W_hh, b_ih, b_hh,
                                     W_fc, b_fc, W_out, b_out, out, Bn);
}

// round 3
// speedup vs baseline: 1.1304x; 1.1304x over previous
#include <cuda_runtime.h>
#include <cstdint>
#include <cstddef>

#define TSTEPS 32
#define INF    27
#define HID    10

// ---------------- constant-memory weight image ----------------
// u64 layout (each u64 = (w,w) duplicated f32x2 multiplier):
//   [0, 1120)      W_ih rows: gate-row r in [0,40), offset r*28 + j, j in [0,27), pads 0
//   [1120, 1600)   W_hh rows: 1120 + r*12 + j, j in [0,10), pads 0
//   [1600, 1640)   bias dup: (b_ih+b_hh)[r]
__constant__ unsigned long long c_w[1640];
// head params as plain floats: [0,50) W_fc, [50,55) b_fc, [55,60) W_out, [60] b_out
__constant__ float c_head[64];

__device__ unsigned long long g_stage_w[1640];
__device__ float g_stage_head[64];

// ---------- packed f32x2 helpers (Blackwell) ----------
__device__ __forceinline__ unsigned long long pk2(float a, float b){
  unsigned long long r;
  asm("mov.b64 %0, {%1, %2};" : "=l"(r) : "f"(a), "f"(b));
  return r;
}
__device__ __forceinline__ float2 unpk2(unsigned long long v){
  float2 r;
  asm("mov.b64 {%0, %1}, %2;" : "=f"(r.x), "=f"(r.y) : "l"(v));
  return r;
}
__device__ __forceinline__ unsigned long long ffma2(unsigned long long a, unsigned long long b, unsigned long long c){
  unsigned long long d;
  asm("fma.rn.f32x2 %0, %1, %2, %3;" : "=l"(d) : "l"(a), "l"(b), "l"(c));
  return d;
}
__device__ __forceinline__ void cp8(uint32_t saddr, const void* gptr){
  asm volatile("cp.async.ca.shared.global [%0], [%1], 8;" :: "r"(saddr), "l"(gptr));
}
// sigmoid / tanh via MUFU.EX2 + MUFU.RCP (near-full precision; rel_err 5e-8 proven)
__device__ __forceinline__ float sigf(float v){
  return __fdividef(1.f, 1.f + __expf(-v));
}
__device__ __forceinline__ float tanhfast(float v){
  return __fdividef(2.f, 1.f + __expf(-2.f*v)) - 1.f;
}

// ---------------- prep: build duplicated weight image ----------------
__global__ void prep_kernel(const float* __restrict__ W_ih, const float* __restrict__ W_hh,
                            const float* __restrict__ b_ih, const float* __restrict__ b_hh,
                            const float* __restrict__ W_fc, const float* __restrict__ b_fc,
                            const float* __restrict__ W_out, const float* __restrict__ b_out){
  int tid = threadIdx.x;
  for (int idx = tid; idx < 40*28; idx += blockDim.x){
    int r = idx / 28, j = idx - r*28;
    float w = (j < 27) ? W_ih[r*27 + j] : 0.f;
    g_stage_w[idx] = pk2(w, w);
  }
  for (int idx = tid; idx < 40*12; idx += blockDim.x){
    int r = idx / 12, j = idx - r*12;
    float w = (j < 10) ? W_hh[r*10 + j] : 0.f;
    g_stage_w[1120 + idx] = pk2(w, w);
  }
  if (tid < 40){ float b = b_ih[tid] + b_hh[tid]; g_stage_w[1600 + tid] = pk2(b, b); }
  if (tid < 50) g_stage_head[tid] = W_fc[tid];
  if (tid < 5) { g_stage_head[50 + tid] = b_fc[tid]; g_stage_head[55 + tid] = W_out[tid]; }
  if (tid == 0) g_stage_head[60] = b_out[0];
}

// ---------------- main: 64 threads/block, 2 batch elems/thread ----------------
__global__ void __launch_bounds__(64) lstm_fused_kernel(
    const float* __restrict__ word, float* __restrict__ out, int Bn)
{
  __shared__ __align__(16) float s_x[2][128*INF];   // double-buffered x staging

  const int tid = threadIdx.x;
  const int blockElem = blockIdx.x * 128;
  const uint32_t sx0 = (uint32_t)__cvta_generic_to_shared(&s_x[0][0]);

  // stage t=0 into buffer 0 (1728 float2 per block-step)
  {
    const float2* src = (const float2*)(word + ((size_t)blockElem) * INF);
    #pragma unroll
    for (int m = 0; m < 27; m++){
      int i2 = m*64 + tid;
      cp8(sx0 + (uint32_t)(i2*8), src + i2);
    }
    asm volatile("cp.async.commit_group;");
  }

  // packed recurrent state
  unsigned long long hp[10], hn[10];
  float c0a[10], c1a[10];
  #pragma unroll
  for (int k = 0; k < 10; k++){ hp[k] = 0ull; c0a[k] = 0.f; c1a[k] = 0.f; }

  const int e0 = 2*tid;

  #pragma unroll 1
  for (int t = 0; t < TSTEPS; t++){
    if (t + 1 < TSTEPS){
      const float2* src = (const float2*)(word + ((size_t)(t+1)*Bn + blockElem) * INF);
      uint32_t dst = sx0 + (uint32_t)(((t+1)&1) * (128*INF*4));
      #pragma unroll
      for (int m = 0; m < 27; m++){
        int i2 = m*64 + tid;
        cp8(dst + (uint32_t)(i2*8), src + i2);
      }
      asm volatile("cp.async.commit_group;");
      asm volatile("cp.async.wait_group 1;");
    } else {
      asm volatile("cp.async.wait_group 0;");
    }
    __syncthreads();

    // pack this thread's 2 elements' x into registers
    const float* xb = &s_x[t & 1][0];
    unsigned long long xj[27];
    #pragma unroll
    for (int j = 0; j < 27; j++)
      xj[j] = pk2(xb[e0*INF + j], xb[e0*INF + INF + j]);

    #pragma unroll
    for (int k = 0; k < 10; k++){
      unsigned long long ai = c_w[1600 + k];
      unsigned long long af = c_w[1600 + k + 10];
      unsigned long long ag = c_w[1600 + k + 20];
      unsigned long long ao = c_w[1600 + k + 30];
      // input contribution: weights from constant port (no L1 traffic)
      #pragma unroll
      for (int j = 0; j < 27; j++){
        ai = ffma2(c_w[(k     )*28 + j], xj[j], ai);
        af = ffma2(c_w[(k + 10)*28 + j], xj[j], af);
        ag = ffma2(c_w[(k + 20)*28 + j], xj[j], ag);
        ao = ffma2(c_w[(k + 30)*28 + j], xj[j], ao);
      }
      // hidden contribution
      #pragma unroll
      for (int j = 0; j < 10; j++){
        ai = ffma2(c_w[1120 + (k     )*12 + j], hp[j], ai);
        af = ffma2(c_w[1120 + (k + 10)*12 + j], hp[j], af);
        ag = ffma2(c_w[1120 + (k + 20)*12 + j], hp[j], ag);
        ao = ffma2(c_w[1120 + (k + 30)*12 + j], hp[j], ao);
      }
      float2 gi = unpk2(ai), gf = unpk2(af), gg = unpk2(ag), go = unpk2(ao);
      float i0 = sigf(gi.x), i1 = sigf(gi.y);
      float f0 = sigf(gf.x), f1 = sigf(gf.y);
      float g0 = tanhfast(gg.x), g1 = tanhfast(gg.y);
      float o0 = sigf(go.x), o1 = sigf(go.y);
      float cn0 = fmaf(f0, c0a[k], i0*g0);
      float cn1 = fmaf(f1, c1a[k], i1*g1);
      float h0  = o0 * tanhfast(cn0);
      float h1  = o1 * tanhfast(cn1);
      c0a[k] = fmaxf(cn0, 0.f);                     // ReLU on carried cell state
      c1a[k] = fmaxf(cn1, 0.f);
      hn[k]  = pk2(fmaxf(h0, 0.f), fmaxf(h1, 0.f)); // ReLU on carried hidden
    }
    #pragma unroll
    for (int k = 0; k < 10; k++) hp[k] = hn[k];
    __syncthreads();   // all reads of this x buffer done before re-staging
  }

  // ---- head: FC(10->5) -> ReLU -> Linear(5->1) -> sigmoid ----
  float h0s[10], h1s[10];
  #pragma unroll
  for (int k = 0; k < 10; k++){ float2 v = unpk2(hp[k]); h0s[k] = v.x; h1s[k] = v.y; }
  float z0 = c_head[60], z1 = c_head[60];
  #pragma unroll
  for (int u = 0; u < 5; u++){
    float y0 = c_head[50 + u], y1 = c_head[50 + u];
    #pragma unroll
    for (int k = 0; k < 10; k++){
      y0 = fmaf(c_head[u*10 + k], h0s[k], y0);
      y1 = fmaf(c_head[u*10 + k], h1s[k], y1);
    }
    y0 = fmaxf(y0, 0.f); y1 = fmaxf(y1, 0.f);
    z0 = fmaf(c_head[55 + u], y0, z0);
    z1 = fmaf(c_head[55 + u], y1, z1);
  }
  const int b0 = blockElem + e0;
  if (b0     < Bn) out[b0]     = sigf(z0);
  if (b0 + 1 < Bn) out[b0 + 1] = sigf(z1);
}

extern "C" void kernel_launch(void* const* d_in, const int* in_sizes, int n_in,
                              void* d_out, int out_size) {
  const float* word  = (const float*)d_in[0];
  const float* W_ih  = (const float*)d_in[1];
  const float* W_hh  = (const float*)d_in[2];
  const float* b_ih  = (const float*)d_in[3];
  const float* b_hh  = (const float*)d_in[4];
  const float* W_fc  = (const float*)d_in[5];
  const float* b_fc  = (const float*)d_in[6];
  const float* W_out = (const float*)d_in[7];
  const float* b_out = (const float*)d_in[8];
  float* out = (float*)d_out;

  const int Bn = in_sizes[0] / (TSTEPS * INF);   // 65536
  const int blocks = (Bn + 127) / 128;           // 512 blocks of 64 threads

  // 1) build duplicated weight image in __device__ staging
  prep_kernel<<<1, 128>>>(W_ih, W_hh, b_ih, b_hh, W_fc, b_fc, W_out, b_out);

  // 2) async D2D copy staging -> constant bank (graph-capturable memcpy nodes)
  void* stage_w = nullptr; void* stage_h = nullptr;
  cudaGetSymbolAddress(&stage_w, g_stage_w);
  cudaGetSymbolAddress(&stage_h, g_stage_head);
  cudaMemcpyToSymbolAsync(c_w, stage_w, sizeof(unsigned long long)*1640, 0,
                          cudaMemcpyDeviceToDevice, 0);
  cudaMemcpyToSymbolAsync(c_head, stage_h, sizeof(float)*64, 0,
                          cudaMemcpyDeviceToDevice, 0);

  // 3) main fused kernel
  lstm_fused_kernel<<<blocks, 64>>>(word, out, Bn);
}

// round 4
// speedup vs baseline: 1.6617x; 1.4700x over previous
#include <cuda_runtime.h>
#include <cstdint>
#include <cstddef>

#define TSTEPS 32
#define INF    27
#define HID    10

__device__ __forceinline__ void cp8(uint32_t saddr, const void* gptr){
  asm volatile("cp.async.ca.shared.global [%0], [%1], 8;" :: "r"(saddr), "l"(gptr));
}
// sigmoid / tanh via MUFU.EX2 + MUFU.RCP (near-full precision; rel_err 5e-8 proven)
__device__ __forceinline__ float sigf(float v){
  return __fdividef(1.f, 1.f + __expf(-v));
}
__device__ __forceinline__ float tanhfast(float v){
  return __fdividef(2.f, 1.f + __expf(-2.f*v)) - 1.f;
}

// 128 threads/block, 1 batch element per thread. Plain scalar fp32 — no inline
// asm in the hot loop, no u64 register pairs, ptxas schedules freely.
__global__ void __launch_bounds__(128) lstm_fused_kernel(
    const float* __restrict__ word,
    const float* __restrict__ W_ih, const float* __restrict__ W_hh,
    const float* __restrict__ b_ih, const float* __restrict__ b_hh,
    const float* __restrict__ W_fc, const float* __restrict__ b_fc,
    const float* __restrict__ W_out, const float* __restrict__ b_out,
    float* __restrict__ out, int Bn)
{
  // scalar weights, rows padded for LDS.128-friendly immediate offsets
  __shared__ __align__(16) float s_wih[40*28];  // row r: r*28 + j, j<27, pad 0
  __shared__ __align__(16) float s_whh[40*12];  // row r: r*12 + j, j<10, pad 0
  __shared__ float s_bias[40];                  // b_ih + b_hh
  __shared__ float s_wfc[50], s_bfc[5], s_wout[5], s_bout[1];
  __shared__ __align__(16) float s_x[2][128*INF];  // double-buffered x staging

  const int tid = threadIdx.x;

  for (int idx = tid; idx < 40*28; idx += 128){
    int r = idx / 28, j = idx - r*28;
    s_wih[idx] = (j < 27) ? W_ih[r*27 + j] : 0.f;
  }
  for (int idx = tid; idx < 40*12; idx += 128){
    int r = idx / 12, j = idx - r*12;
    s_whh[idx] = (j < 10) ? W_hh[r*10 + j] : 0.f;
  }
  if (tid < 40) s_bias[tid] = b_ih[tid] + b_hh[tid];
  if (tid < 50) s_wfc[tid] = W_fc[tid];
  if (tid < 5) { s_bfc[tid] = b_fc[tid]; s_wout[tid] = W_out[tid]; }
  if (tid == 0) s_bout[0] = b_out[0];

  const int blockElem = blockIdx.x * 128;
  const uint32_t sx0 = (uint32_t)__cvta_generic_to_shared(&s_x[0][0]);

  // stage t=0 into buffer 0 (1728 float2 per block-step, 128 threads)
  {
    const float2* src = (const float2*)(word + ((size_t)blockElem) * INF);
    #pragma unroll
    for (int m = 0; m < 14; m++){
      int i2 = m*128 + tid;
      if (i2 < 1728) cp8(sx0 + (uint32_t)(i2*8), src + i2);
    }
    asm volatile("cp.async.commit_group;");
  }

  float h[10], c[10];
  #pragma unroll
  for (int k = 0; k < 10; k++){ h[k] = 0.f; c[k] = 0.f; }

  #pragma unroll 1
  for (int t = 0; t < TSTEPS; t++){
    if (t + 1 < TSTEPS){
      const float2* src = (const float2*)(word + ((size_t)(t+1)*Bn + blockElem) * INF);
      uint32_t dst = sx0 + (uint32_t)(((t+1)&1) * (128*INF*4));
      #pragma unroll
      for (int m = 0; m < 14; m++){
        int i2 = m*128 + tid;
        if (i2 < 1728) cp8(dst + (uint32_t)(i2*8), src + i2);
      }
      asm volatile("cp.async.commit_group;");
      asm volatile("cp.async.wait_group 1;");
    } else {
      asm volatile("cp.async.wait_group 0;");
    }
    __syncthreads();

    // this thread's x row into registers (stride 27 across lanes: 27 coprime
    // with 32 banks -> conflict-free permutation per j)
    const float* xb = &s_x[t & 1][tid * INF];
    float xr[27];
    #pragma unroll
    for (int j = 0; j < 27; j++) xr[j] = xb[j];

    float hn[10];
    #pragma unroll
    for (int k = 0; k < 10; k++){
      float ai = s_bias[k];
      float af = s_bias[k + 10];
      float ag = s_bias[k + 20];
      float ao = s_bias[k + 30];
      #pragma unroll
      for (int j = 0; j < 27; j++){
        float xv = xr[j];
        ai = fmaf(s_wih[(k     )*28 + j], xv, ai);
        af = fmaf(s_wih[(k + 10)*28 + j], xv, af);
        ag = fmaf(s_wih[(k + 20)*28 + j], xv, ag);
        ao = fmaf(s_wih[(k + 30)*28 + j], xv, ao);
      }
      #pragma unroll
      for (int j = 0; j < 10; j++){
        float hv = h[j];
        ai = fmaf(s_whh[(k     )*12 + j], hv, ai);
        af = fmaf(s_whh[(k + 10)*12 + j], hv, af);
        ag = fmaf(s_whh[(k + 20)*12 + j], hv, ag);
        ao = fmaf(s_whh[(k + 30)*12 + j], hv, ao);
      }
      float iv = sigf(ai);
      float fv = sigf(af);
      float gv = tanhfast(ag);
      float ov = sigf(ao);
      float cn = fmaf(fv, c[k], iv * gv);
      float hv = ov * tanhfast(cn);
      c[k]  = fmaxf(cn, 0.f);        // ReLU on carried cell state
      hn[k] = fmaxf(hv, 0.f);        // ReLU on carried hidden
    }
    #pragma unroll
    for (int k = 0; k < 10; k++) h[k] = hn[k];
    __syncthreads();   // all reads of this x buffer done before re-staging
  }

  // ---- head: FC(10->5) -> ReLU -> Linear(5->1) -> sigmoid ----
  float z = s_bout[0];
  #pragma unroll
  for (int u = 0; u < 5; u++){
    float y = s_bfc[u];
    #pragma unroll
    for (int k = 0; k < 10; k++)
      y = fmaf(s_wfc[u*10 + k], h[k], y);
    z = fmaf(s_wout[u], fmaxf(y, 0.f), z);
  }
  const int b0 = blockElem + tid;
  if (b0 < Bn) out[b0] = sigf(z);
}

extern "C" void kernel_launch(void* const* d_in, const int* in_sizes, int n_in,
                              void* d_out, int out_size) {
  const float* word  = (const float*)d_in[0];
  const float* W_ih  = (const float*)d_in[1];
  const float* W_hh  = (const float*)d_in[2];
  const float* b_ih  = (const float*)d_in[3];
  const float* b_hh  = (const float*)d_in[4];
  const float* W_fc  = (const float*)d_in[5];
  const float* b_fc  = (const float*)d_in[6];
  const float* W_out = (const float*)d_in[7];
  const float* b_out = (const float*)d_in[8];
  float* out = (float*)d_out;

  const int Bn = in_sizes[0] / (TSTEPS * INF);   // 65536
  const int blocks = (Bn + 127) / 128;           // 512 blocks of 128 threads

  lstm_fused_kernel<<<blocks, 128>>>(word, W_ih, W_hh, b_ih, b_hh,
                                     W_fc, b_fc, W_out, b_out, out, Bn);
}

// round 5
// speedup vs baseline: 1.7196x; 1.0348x over previous
#include <cuda_runtime.h>
#include <cstdint>
#include <cstddef>

#define TSTEPS 32
#define INF    27
#define HID    10

__device__ __forceinline__ void cp8(uint32_t saddr, const void* gptr){
  asm volatile("cp.async.ca.shared.global [%0], [%1], 8;" :: "r"(saddr), "l"(gptr));
}
// sigmoid / tanh via MUFU.EX2 + MUFU.RCP (near-full precision; rel_err 5e-8 proven)
__device__ __forceinline__ float sigf(float v){
  return __fdividef(1.f, 1.f + __expf(-v));
}
__device__ __forceinline__ float tanhfast(float v){
  return __fdividef(2.f, 1.f + __expf(-2.f*v)) - 1.f;
}

// 64 threads/block, 2 batch elements per thread (t and t+64 within the block's
// 128-element tile) so every weight LDS feeds two FMAs. Plain scalar fp32.
__global__ void __launch_bounds__(64) lstm_fused_kernel(
    const float* __restrict__ word,
    const float* __restrict__ W_ih, const float* __restrict__ W_hh,
    const float* __restrict__ b_ih, const float* __restrict__ b_hh,
    const float* __restrict__ W_fc, const float* __restrict__ b_fc,
    const float* __restrict__ W_out, const float* __restrict__ b_out,
    float* __restrict__ out, int Bn)
{
  // scalar weights, rows padded for LDS.128-friendly immediate offsets
  __shared__ __align__(16) float s_wih[40*28];  // row r: r*28 + j, j<27, pad 0
  __shared__ __align__(16) float s_whh[40*12];  // row r: r*12 + j, j<10, pad 0
  __shared__ float s_bias[40];                  // b_ih + b_hh
  __shared__ float s_wfc[50], s_bfc[5], s_wout[5], s_bout[1];
  __shared__ __align__(16) float s_x[2][128*INF];  // double-buffered x staging

  const int tid = threadIdx.x;

  for (int idx = tid; idx < 40*28; idx += 64){
    int r = idx / 28, j = idx - r*28;
    s_wih[idx] = (j < 27) ? W_ih[r*27 + j] : 0.f;
  }
  for (int idx = tid; idx < 40*12; idx += 64){
    int r = idx / 12, j = idx - r*12;
    s_whh[idx] = (j < 10) ? W_hh[r*10 + j] : 0.f;
  }
  if (tid < 40) s_bias[tid] = b_ih[tid] + b_hh[tid];
  if (tid < 50) s_wfc[tid] = W_fc[tid];
  if (tid < 5) { s_bfc[tid] = b_fc[tid]; s_wout[tid] = W_out[tid]; }
  if (tid == 0) s_bout[0] = b_out[0];

  const int blockElem = blockIdx.x * 128;
  const uint32_t sx0 = (uint32_t)__cvta_generic_to_shared(&s_x[0][0]);

  // stage t=0 into buffer 0 (1728 float2 per block-step, 64 threads)
  {
    const float2* src = (const float2*)(word + ((size_t)blockElem) * INF);
    #pragma unroll
    for (int m = 0; m < 27; m++){
      int i2 = m*64 + tid;
      cp8(sx0 + (uint32_t)(i2*8), src + i2);
    }
    asm volatile("cp.async.commit_group;");
  }

  // two elements' recurrent state
  float hA[10], cA[10], hB[10], cB[10];
  #pragma unroll
  for (int k = 0; k < 10; k++){ hA[k]=0.f; cA[k]=0.f; hB[k]=0.f; cB[k]=0.f; }

  #pragma unroll 1
  for (int t = 0; t < TSTEPS; t++){
    if (t + 1 < TSTEPS){
      const float2* src = (const float2*)(word + ((size_t)(t+1)*Bn + blockElem) * INF);
      uint32_t dst = sx0 + (uint32_t)(((t+1)&1) * (128*INF*4));
      #pragma unroll
      for (int m = 0; m < 27; m++){
        int i2 = m*64 + tid;
        cp8(dst + (uint32_t)(i2*8), src + i2);
      }
      asm volatile("cp.async.commit_group;");
      asm volatile("cp.async.wait_group 1;");
    } else {
      asm volatile("cp.async.wait_group 0;");
    }
    __syncthreads();

    // x rows for elements tid and tid+64 (stride-27 rows: bank-conflict-free)
    const float* xbA = &s_x[t & 1][tid * INF];
    const float* xbB = &s_x[t & 1][(tid + 64) * INF];
    float xA[27], xB[27];
    #pragma unroll
    for (int j = 0; j < 27; j++){ xA[j] = xbA[j]; xB[j] = xbB[j]; }

    float hnA[10], hnB[10];
    #pragma unroll
    for (int k = 0; k < 10; k++){
      float ai0 = s_bias[k],      ai1 = ai0;
      float af0 = s_bias[k + 10], af1 = af0;
      float ag0 = s_bias[k + 20], ag1 = ag0;
      float ao0 = s_bias[k + 30], ao1 = ao0;
      #pragma unroll
      for (int j = 0; j < 27; j++){
        float wi = s_wih[(k     )*28 + j];
        float wf = s_wih[(k + 10)*28 + j];
        float wg = s_wih[(k + 20)*28 + j];
        float wo = s_wih[(k + 30)*28 + j];
        float xa = xA[j], xb = xB[j];
        ai0 = fmaf(wi, xa, ai0);  ai1 = fmaf(wi, xb, ai1);
        af0 = fmaf(wf, xa, af0);  af1 = fmaf(wf, xb, af1);
        ag0 = fmaf(wg, xa, ag0);  ag1 = fmaf(wg, xb, ag1);
        ao0 = fmaf(wo, xa, ao0);  ao1 = fmaf(wo, xb, ao1);
      }
      #pragma unroll
      for (int j = 0; j < 10; j++){
        float ui = s_whh[(k     )*12 + j];
        float uf = s_whh[(k + 10)*12 + j];
        float ug = s_whh[(k + 20)*12 + j];
        float uo = s_whh[(k + 30)*12 + j];
        float ha = hA[j], hb = hB[j];
        ai0 = fmaf(ui, ha, ai0);  ai1 = fmaf(ui, hb, ai1);
        af0 = fmaf(uf, ha, af0);  af1 = fmaf(uf, hb, af1);
        ag0 = fmaf(ug, ha, ag0);  ag1 = fmaf(ug, hb, ag1);
        ao0 = fmaf(uo, ha, ao0);  ao1 = fmaf(uo, hb, ao1);
      }
      float i0 = sigf(ai0), i1 = sigf(ai1);
      float f0 = sigf(af0), f1 = sigf(af1);
      float g0 = tanhfast(ag0), g1 = tanhfast(ag1);
      float o0 = sigf(ao0), o1 = sigf(ao1);
      float cn0 = fmaf(f0, cA[k], i0*g0);
      float cn1 = fmaf(f1, cB[k], i1*g1);
      float hv0 = o0 * tanhfast(cn0);
      float hv1 = o1 * tanhfast(cn1);
      cA[k]  = fmaxf(cn0, 0.f);       // ReLU on carried cell state
      cB[k]  = fmaxf(cn1, 0.f);
      hnA[k] = fmaxf(hv0, 0.f);       // ReLU on carried hidden
      hnB[k] = fmaxf(hv1, 0.f);
    }
    #pragma unroll
    for (int k = 0; k < 10; k++){ hA[k] = hnA[k]; hB[k] = hnB[k]; }
    __syncthreads();   // all reads of this x buffer done before re-staging
  }

  // ---- head: FC(10->5) -> ReLU -> Linear(5->1) -> sigmoid ----
  float z0 = s_bout[0], z1 = s_bout[0];
  #pragma unroll
  for (int u = 0; u < 5; u++){
    float y0 = s_bfc[u], y1 = s_bfc[u];
    #pragma unroll
    for (int k = 0; k < 10; k++){
      float w = s_wfc[u*10 + k];
      y0 = fmaf(w, hA[k], y0);
      y1 = fmaf(w, hB[k], y1);
    }
    z0 = fmaf(s_wout[u], fmaxf(y0, 0.f), z0);
    z1 = fmaf(s_wout[u], fmaxf(y1, 0.f), z1);
  }
  const int b0 = blockElem + tid;
  if (b0      < Bn) out[b0]      = sigf(z0);
  if (b0 + 64 < Bn) out[b0 + 64] = sigf(z1);
}

extern "C" void kernel_launch(void* const* d_in, const int* in_sizes, int n_in,
                              void* d_out, int out_size) {
  const float* word  = (const float*)d_in[0];
  const float* W_ih  = (const float*)d_in[1];
  const float* W_hh  = (const float*)d_in[2];
  const float* b_ih  = (const float*)d_in[3];
  const float* b_hh  = (const float*)d_in[4];
  const float* W_fc  = (const float*)d_in[5];
  const float* b_fc  = (const float*)d_in[6];
  const float* W_out = (const float*)d_in[7];
  const float* b_out = (const float*)d_in[8];
  float* out = (float*)d_out;

  const int Bn = in_sizes[0] / (TSTEPS * INF);   // 65536
  const int blocks = (Bn + 127) / 128;           // 512 blocks of 64 threads

  lstm_fused_kernel<<<blocks, 64>>>(word, W_ih, W_hh, b_ih, b_hh,
                                    W_fc, b_fc, W_out, b_out, out, Bn);
}

// round 6
// speedup vs baseline: 1.7439x; 1.0141x over previous
#include <cuda_runtime.h>
#include <cstdint>
#include <cstddef>

#define TSTEPS 32
#define INF    27
#define HID    10

__device__ __forceinline__ void cp8(uint32_t saddr, const void* gptr){
  asm volatile("cp.async.ca.shared.global [%0], [%1], 8;" :: "r"(saddr), "l"(gptr));
}
// sigmoid / tanh via MUFU.EX2 + MUFU.RCP (near-full precision; rel_err 5e-8 proven)
__device__ __forceinline__ float sigf(float v){
  return __fdividef(1.f, 1.f + __expf(-v));
}
__device__ __forceinline__ float tanhfast(float v){
  return __fdividef(2.f, 1.f + __expf(-2.f*v)) - 1.f;
}

// 128 threads/block. Lane pairs (2p, 2p+1) share batch elements {2p, 2p+1};
// lane parity selects which 5 hidden units it computes. Each thread: 2 elems
// x 5 k -> same FMA/thread as R4, half the weight LDS, 2048 warps total.
// Plain scalar fp32 hot loop (no inline-asm math).
__global__ void __launch_bounds__(128) lstm_fused_kernel(
    const float* __restrict__ word,
    const float* __restrict__ W_ih, const float* __restrict__ W_hh,
    const float* __restrict__ b_ih, const float* __restrict__ b_hh,
    const float* __restrict__ W_fc, const float* __restrict__ b_fc,
    const float* __restrict__ W_out, const float* __restrict__ b_out,
    float* __restrict__ out, int Bn)
{
  // scalar weights, rows padded for LDS.128-friendly immediate offsets
  __shared__ __align__(16) float s_wih[40*28];  // row r: r*28 + j, j<27, pad 0
  __shared__ __align__(16) float s_whh[40*12];  // row r: r*12 + j, j<10, pad 0
  __shared__ float s_bias[40];                  // b_ih + b_hh
  __shared__ float s_wfc[50], s_bfc[5], s_wout[5], s_bout[1];
  __shared__ __align__(16) float s_x[2][128*INF];  // double-buffered x staging

  const int tid  = threadIdx.x;
  const int half = tid & 1;        // which 5 k's this lane owns (0..4 or 5..9)
  const int p    = tid >> 1;       // pair index (0..63)
  const int kb   = half * 5;

  for (int idx = tid; idx < 40*28; idx += 128){
    int r = idx / 28, j = idx - r*28;
    s_wih[idx] = (j < 27) ? W_ih[r*27 + j] : 0.f;
  }
  for (int idx = tid; idx < 40*12; idx += 128){
    int r = idx / 12, j = idx - r*12;
    s_whh[idx] = (j < 10) ? W_hh[r*10 + j] : 0.f;
  }
  if (tid < 40) s_bias[tid] = b_ih[tid] + b_hh[tid];
  if (tid < 50) s_wfc[tid] = W_fc[tid];
  if (tid < 5) { s_bfc[tid] = b_fc[tid]; s_wout[tid] = W_out[tid]; }
  if (tid == 0) s_bout[0] = b_out[0];

  const int blockElem = blockIdx.x * 128;
  const uint32_t sx0 = (uint32_t)__cvta_generic_to_shared(&s_x[0][0]);

  // stage t=0 into buffer 0 (1728 float2 per block-step, 128 threads)
  {
    const float2* src = (const float2*)(word + ((size_t)blockElem) * INF);
    #pragma unroll
    for (int m = 0; m < 14; m++){
      int i2 = m*128 + tid;
      if (i2 < 1728) cp8(sx0 + (uint32_t)(i2*8), src + i2);
    }
    asm volatile("cp.async.commit_group;");
  }

  // full h for both elements (rebuilt each step via shfl exchange),
  // own-c only (5 k x 2 elems)
  float hA[10], hB[10], cA[5], cB[5];
  #pragma unroll
  for (int k = 0; k < 10; k++){ hA[k]=0.f; hB[k]=0.f; }
  #pragma unroll
  for (int k = 0; k < 5;  k++){ cA[k]=0.f; cB[k]=0.f; }

  // lane-local weight bases (kb is uniform per lane; hoisted out of the loop)
  const float* wih_b  = s_wih + kb*28;
  const float* whh_b  = s_whh + kb*12;
  const float* bias_b = s_bias + kb;

  #pragma unroll 1
  for (int t = 0; t < TSTEPS; t++){
    if (t + 1 < TSTEPS){
      const float2* src = (const float2*)(word + ((size_t)(t+1)*Bn + blockElem) * INF);
      uint32_t dst = sx0 + (uint32_t)(((t+1)&1) * (128*INF*4));
      #pragma unroll
      for (int m = 0; m < 14; m++){
        int i2 = m*128 + tid;
        if (i2 < 1728) cp8(dst + (uint32_t)(i2*8), src + i2);
      }
      asm volatile("cp.async.commit_group;");
      asm volatile("cp.async.wait_group 1;");
    } else {
      asm volatile("cp.async.wait_group 0;");
    }
    __syncthreads();

    // x rows for pair elements 2p and 2p+1 (both lanes of a pair read the
    // same addresses -> 2-way broadcast; row stride 27 coprime w/ 32 banks)
    const float* xbA = &s_x[t & 1][(2*p    ) * INF];
    const float* xbB = &s_x[t & 1][(2*p + 1) * INF];
    float xA[27], xB[27];
    #pragma unroll
    for (int j = 0; j < 27; j++){ xA[j] = xbA[j]; xB[j] = xbB[j]; }

    float hnA[5], hnB[5];
    #pragma unroll
    for (int kk = 0; kk < 5; kk++){
      float ai0 = bias_b[kk],      ai1 = ai0;
      float af0 = bias_b[kk + 10], af1 = af0;
      float ag0 = bias_b[kk + 20], ag1 = ag0;
      float ao0 = bias_b[kk + 30], ao1 = ao0;
      #pragma unroll
      for (int j = 0; j < 27; j++){
        float wi = wih_b[(kk     )*28 + j];
        float wf = wih_b[(kk + 10)*28 + j];
        float wg = wih_b[(kk + 20)*28 + j];
        float wo = wih_b[(kk + 30)*28 + j];
        float xa = xA[j], xb = xB[j];
        ai0 = fmaf(wi, xa, ai0);  ai1 = fmaf(wi, xb, ai1);
        af0 = fmaf(wf, xa, af0);  af1 = fmaf(wf, xb, af1);
        ag0 = fmaf(wg, xa, ag0);  ag1 = fmaf(wg, xb, ag1);
        ao0 = fmaf(wo, xa, ao0);  ao1 = fmaf(wo, xb, ao1);
      }
      #pragma unroll
      for (int j = 0; j < 10; j++){
        float ui = whh_b[(kk     )*12 + j];
        float uf = whh_b[(kk + 10)*12 + j];
        float ug = whh_b[(kk + 20)*12 + j];
        float uo = whh_b[(kk + 30)*12 + j];
        float ha = hA[j], hb = hB[j];
        ai0 = fmaf(ui, ha, ai0);  ai1 = fmaf(ui, hb, ai1);
        af0 = fmaf(uf, ha, af0);  af1 = fmaf(uf, hb, af1);
        ag0 = fmaf(ug, ha, ag0);  ag1 = fmaf(ug, hb, ag1);
        ao0 = fmaf(uo, ha, ao0);  ao1 = fmaf(uo, hb, ao1);
      }
      float i0 = sigf(ai0), i1 = sigf(ai1);
      float f0 = sigf(af0), f1 = sigf(af1);
      float g0 = tanhfast(ag0), g1 = tanhfast(ag1);
      float o0 = sigf(ao0), o1 = sigf(ao1);
      float cn0 = fmaf(f0, cA[kk], i0*g0);
      float cn1 = fmaf(f1, cB[kk], i1*g1);
      float hv0 = o0 * tanhfast(cn0);
      float hv1 = o1 * tanhfast(cn1);
      cA[kk]  = fmaxf(cn0, 0.f);       // ReLU on carried cell state
      cB[kk]  = fmaxf(cn1, 0.f);
      hnA[kk] = fmaxf(hv0, 0.f);       // ReLU on carried hidden
      hnB[kk] = fmaxf(hv1, 0.f);
    }
    // exchange halves with pair partner -> full h for both elements
    const int ob = 5 - kb;             // partner's k-base (0 <-> 5)
    #pragma unroll
    for (int kk = 0; kk < 5; kk++){
      float oA = __shfl_xor_sync(0xFFFFFFFFu, hnA[kk], 1);
      float oB = __shfl_xor_sync(0xFFFFFFFFu, hnB[kk], 1);
      hA[kb + kk] = hnA[kk];  hA[ob + kk] = oA;
      hB[kb + kk] = hnB[kk];  hB[ob + kk] = oB;
    }
    __syncthreads();   // all reads of this x buffer done before re-staging
  }

  // ---- head: FC(10->5) -> ReLU -> Linear(5->1) -> sigmoid ----
  if (half == 0){
    float z0 = s_bout[0], z1 = s_bout[0];
    #pragma unroll
    for (int u = 0; u < 5; u++){
      float y0 = s_bfc[u], y1 = s_bfc[u];
      #pragma unroll
      for (int k = 0; k < 10; k++){
        float w = s_wfc[u*10 + k];
        y0 = fmaf(w, hA[k], y0);
        y1 = fmaf(w, hB[k], y1);
      }
      z0 = fmaf(s_wout[u], fmaxf(y0, 0.f), z0);
      z1 = fmaf(s_wout[u], fmaxf(y1, 0.f), z1);
    }
    const int b0 = blockElem + 2*p;
    if (b0 + 1 < Bn){
      float2 v; v.x = sigf(z0); v.y = sigf(z1);
      *(float2*)(out + b0) = v;                 // coalesced 8B store
    } else if (b0 < Bn){
      out[b0] = sigf(z0);
    }
  }
}

extern "C" void kernel_launch(void* const* d_in, const int* in_sizes, int n_in,
                              void* d_out, int out_size) {
  const float* word  = (const float*)d_in[0];
  const float* W_ih  = (const float*)d_in[1];
  const float* W_hh  = (const float*)d_in[2];
  const float* b_ih  = (const float*)d_in[3];
  const float* b_hh  = (const float*)d_in[4];
  const float* W_fc  = (const float*)d_in[5];
  const float* b_fc  = (const float*)d_in[6];
  const float* W_out = (const float*)d_in[7];
  const float* b_out = (const float*)d_in[8];
  float* out = (float*)d_out;

  const int Bn = in_sizes[0] / (TSTEPS * INF);   // 65536
  const int blocks = (Bn + 127) / 128;           // 512 blocks of 128 threads

  lstm_fused_kernel<<<blocks, 128>>>(word, W_ih, W_hh, b_ih, b_hh,
                                     W_fc, b_fc, W_out, b_out, out, Bn);
}